// round 9
// baseline (speedup 1.0000x reference)
#include <cuda_runtime.h>
#include <cuda_fp16.h>
#include <cstdint>

#define B_    32
#define M_    512
#define S_    10
#define V_    32000
#define D_    128

#define GA_BLKS 2048          // gather blocks: 256 thr, 1 warp per (b,m), tables C1..C3
#define GE_BLKS 200           // GEMM blocks: dot0 = C0 x u0
#define GE_ROWS (V_ / GE_BLKS)   // 160 rows per GEMM block (8 warps x 20 rows)
#define FSPL  16              // m-splits per batch -> 512 blocks, 32 m/block
#define FBLK  (B_ * FSPL)

// Bags for tables 1..3 in fp16, packed 4 dims per uint2.
__device__ __align__(16) uint2 g_bagh[3u * B_ * M_ * (D_ / 4)];   // 12.6 MB
__device__ __align__(16) float g_dot0[V_ * B_];        // dot0[v][b] = C0[v]·u0[b] (4 MB)
__device__ __align__(16) float g_part0[FBLK * D_];     // hop-0 partials (k_F0)
__device__ float g_den0[FBLK];
__device__ __align__(16) float g_partF[FBLK * D_];     // hop partials (k_F1/k_F2)
__device__ float g_denF[FBLK];
__device__ __align__(16) float g_u[B_ * D_];           // u1 (published by k_F1)
__device__ unsigned int g_cnt[B_];                     // k_F2 arrival counters (self-reset)

__device__ __forceinline__ float warpSum(float v) {
    #pragma unroll
    for (int o = 16; o > 0; o >>= 1) v += __shfl_xor_sync(0xffffffffu, v, o);
    return v;
}
__device__ __forceinline__ uint2 pack4(float4 v) {
    __half2 lo = __floats2half2_rn(v.x, v.y);
    __half2 hi = __floats2half2_rn(v.z, v.w);
    uint2 r;
    r.x = *reinterpret_cast<unsigned*>(&lo);
    r.y = *reinterpret_cast<unsigned*>(&hi);
    return r;
}
__device__ __forceinline__ float4 unpack4(uint2 p) {
    __half2 lo = *reinterpret_cast<__half2*>(&p.x);
    __half2 hi = *reinterpret_cast<__half2*>(&p.y);
    float2 l = __half22float2(lo);
    float2 h = __half22float2(hi);
    return make_float4(l.x, l.y, h.x, h.y);
}

// ---------------------------------------------------------------------------
// kA: heterogeneous grid.
//   blocks [0, GA_BLKS): gather — one warp per (b,m), tables C1,C2,C3 -> fp16
//   bags. No C0 traffic (saved 84 MB of LTS bytes).
//   blocks [GA_BLKS, GA_BLKS+GE_BLKS): dot0 GEMM — C0[v]·u0[b] for all v,b,
//   sequential C0 reads, FMA-pipe work overlapped under the L2-bound gather.
// ---------------------------------------------------------------------------
__global__ void __launch_bounds__(256) kA(const int* __restrict__ story,
                                          const float* __restrict__ hidden,
                                          const float* __restrict__ C)
{
    // GEMM staging (reserved by all blocks; gather needs no smem; 33 KB -> 6 blocks/SM)
    __shared__ __align__(16) float4 s_stage[8][4][32];   // 8 warps x 4 rows x 128 dims
    __shared__ __align__(16) float4 s_u0[32][33];        // [d4][b], padded: conflict-free

    const int tid  = threadIdx.x;
    const int lane = tid & 31;
    const int wid  = tid >> 5;

    const float4* C4 = reinterpret_cast<const float4*>(C);
    const size_t tabstr = (size_t)V_ * (D_ / 4);

    if (blockIdx.x < GA_BLKS) {
        // ---------------- gather: tables C1..C3, 1 warp per (b,m) ----------
        const int g = blockIdx.x * 8 + wid;
        const int b = g >> 9;
        const int m = g & (M_ - 1);

        int tok = 0;
        if (lane < S_) tok = story[((size_t)b * M_ + m) * S_ + lane];

        float4 a1 = make_float4(0.f, 0.f, 0.f, 0.f);
        float4 a2 = a1, a3 = a1;
        #pragma unroll
        for (int s = 0; s < S_; s++) {
            const int t = __shfl_sync(0xffffffffu, tok, s);
            const size_t idx = (size_t)t * (D_ / 4) + lane;
            const float4 r1 = C4[idx + tabstr];
            const float4 r2 = C4[idx + 2 * tabstr];
            const float4 r3 = C4[idx + 3 * tabstr];
            a1.x += r1.x; a1.y += r1.y; a1.z += r1.z; a1.w += r1.w;
            a2.x += r2.x; a2.y += r2.y; a2.z += r2.z; a2.w += r2.w;
            a3.x += r3.x; a3.y += r3.y; a3.z += r3.z; a3.w += r3.w;
        }
        const size_t row  = ((size_t)b * M_ + m) * (D_ / 4) + lane;
        const size_t bstr = (size_t)B_ * M_ * (D_ / 4);
        g_bagh[row]            = pack4(a1);   // C1
        g_bagh[row + bstr]     = pack4(a2);   // C2
        g_bagh[row + 2 * bstr] = pack4(a3);   // C3
    } else {
        // ---------------- dot0 GEMM: 160 rows/block, 20 rows/warp ----------
        // Load u0 into padded smem: s_u0[d4][b] = hidden[b][4*d4 .. 4*d4+3]
        for (int i = tid; i < 32 * 32; i += 256) {
            const int d4 = i >> 5, b = i & 31;
            s_u0[d4][b] = reinterpret_cast<const float4*>(hidden)[(size_t)b * 32 + d4];
        }
        __syncthreads();

        const int vwarp = (blockIdx.x - GA_BLKS) * GE_ROWS + wid * (GE_ROWS / 8);
        #pragma unroll 1
        for (int it = 0; it < GE_ROWS / 8 / 4; it++) {   // 20/4 = 5 iters of 4 rows
            const int v0 = vwarp + it * 4;
            #pragma unroll
            for (int k = 0; k < 4; k++)
                s_stage[wid][k][lane] = C4[(size_t)(v0 + k) * 32 + lane];   // C0 rows
            __syncwarp();
            float acc0 = 0.f, acc1 = 0.f, acc2 = 0.f, acc3 = 0.f;
            #pragma unroll
            for (int d4 = 0; d4 < 32; d4++) {
                const float4 u = s_u0[d4][lane];           // lane = batch b
                const float4 r0 = s_stage[wid][0][d4];     // broadcast
                const float4 r1 = s_stage[wid][1][d4];
                const float4 r2 = s_stage[wid][2][d4];
                const float4 r3 = s_stage[wid][3][d4];
                acc0 += r0.x * u.x + r0.y * u.y + r0.z * u.z + r0.w * u.w;
                acc1 += r1.x * u.x + r1.y * u.y + r1.z * u.z + r1.w * u.w;
                acc2 += r2.x * u.x + r2.y * u.y + r2.z * u.z + r2.w * u.w;
                acc3 += r3.x * u.x + r3.y * u.y + r3.z * u.z + r3.w * u.w;
            }
            __syncwarp();
            g_dot0[(size_t)(v0 + 0) * B_ + lane] = acc0;
            g_dot0[(size_t)(v0 + 1) * B_ + lane] = acc1;
            g_dot0[(size_t)(v0 + 2) * B_ + lane] = acc2;
            g_dot0[(size_t)(v0 + 3) * B_ + lane] = acc3;
        }
    }
}

// ---------------------------------------------------------------------------
// k_F0: hop-0 body. Per m: logit0 = sum_s dot0[tok][b] (warp gather of 10
// scalars), e = exp, partial num += e * bagC1[m], den += e -> 16 partials/batch.
// ---------------------------------------------------------------------------
__global__ void __launch_bounds__(256) k_F0(const int* __restrict__ story)
{
    __shared__ __align__(16) float s_pt[8][D_];
    __shared__ float s_den[8];

    const int blk  = blockIdx.x;
    const int b    = blk / FSPL;
    const int sp   = blk % FSPL;
    const int tid  = threadIdx.x;
    const int lane = tid & 31;
    const int wid  = tid >> 5;

    float4 acc = make_float4(0.f, 0.f, 0.f, 0.f);
    float den = 0.f;
    #pragma unroll
    for (int i = 0; i < 4; i++) {
        const int m = sp * 32 + wid * 4 + i;
        float v = 0.f;
        if (lane < S_) {
            const int t = story[((size_t)b * M_ + m) * S_ + lane];
            v = g_dot0[(size_t)t * B_ + b];
        }
        v = warpSum(v);                      // logit0
        const float e = __expf(v);
        const float4 bg = unpack4(g_bagh[((size_t)b * M_ + m) * (D_ / 4) + lane]); // C1
        acc.x += e * bg.x; acc.y += e * bg.y;
        acc.z += e * bg.z; acc.w += e * bg.w;
        den += e;
    }
    reinterpret_cast<float4*>(&s_pt[wid][0])[lane] = acc;
    if (lane == 0) s_den[wid] = den;
    __syncthreads();

    if (tid < D_) {
        float v = 0.f;
        #pragma unroll
        for (int k = 0; k < 8; k++) v += s_pt[k][tid];
        g_part0[(size_t)blk * D_ + tid] = v;
    }
    if (tid == 0) {
        float dn = 0.f;
        #pragma unroll
        for (int k = 0; k < 8; k++) dn += s_den[k];
        g_den0[blk] = dn;
    }
}

// ---------------------------------------------------------------------------
// k_F1: u1 = hidden + reduce16(hop-0 partials) [redundant per block, 2-level];
// hop-1 pass (C1 -> logit1, C2 -> num); write hop-1 partials; sp==0 publishes u1.
// ---------------------------------------------------------------------------
__global__ void __launch_bounds__(256) k_F1(const float* __restrict__ hidden)
{
    __shared__ __align__(16) float s_u[D_];
    __shared__ __align__(16) float s_n[2][D_];
    __shared__ float s_dn[2];
    __shared__ __align__(16) float s_pt[8][D_];
    __shared__ float s_den[8];

    const int blk  = blockIdx.x;
    const int b    = blk / FSPL;
    const int sp   = blk % FSPL;
    const int tid  = threadIdx.x;
    const int lane = tid & 31;
    const int wid  = tid >> 5;

    {
        const int dim  = tid & 127;
        const int half = tid >> 7;
        const int k0   = half * 8;
        float dn = 0.f, num = 0.f;
        #pragma unroll
        for (int k = k0; k < k0 + 8; k++) {
            dn  += g_den0[b * FSPL + k];
            num += g_part0[((size_t)b * FSPL + k) * D_ + dim];
        }
        s_n[half][dim] = num;
        if (dim == 0) s_dn[half] = dn;
    }
    __syncthreads();
    if (tid < D_) {
        s_u[tid] = hidden[(size_t)b * D_ + tid]
                 + (s_n[0][tid] + s_n[1][tid]) / (s_dn[0] + s_dn[1]);
        if (sp == 0) g_u[(size_t)b * D_ + tid] = s_u[tid];
    }
    __syncthreads();

    const float4 u4 = reinterpret_cast<const float4*>(s_u)[lane];
    const size_t bstr  = (size_t)B_ * M_ * (D_ / 4);
    const size_t rbase = (size_t)(b * M_ + sp * 32) * (D_ / 4) + lane;

    float4 acc = make_float4(0.f, 0.f, 0.f, 0.f);
    float den = 0.f;
    #pragma unroll
    for (int i = 0; i < 4; i++) {
        const int ml = wid * 4 + i;
        const size_t r = rbase + (size_t)ml * (D_ / 4);
        const float4 va = unpack4(g_bagh[r]);               // C1
        const float4 vb = unpack4(g_bagh[bstr + r]);        // C2
        float d = va.x * u4.x + va.y * u4.y + va.z * u4.z + va.w * u4.w;
        d = warpSum(d);
        const float e = __expf(d);
        acc.x += e * vb.x; acc.y += e * vb.y;
        acc.z += e * vb.z; acc.w += e * vb.w;
        den += e;
    }
    reinterpret_cast<float4*>(&s_pt[wid][0])[lane] = acc;
    if (lane == 0) s_den[wid] = den;
    __syncthreads();

    if (tid < D_) {
        float v = 0.f;
        #pragma unroll
        for (int k = 0; k < 8; k++) v += s_pt[k][tid];
        g_partF[(size_t)blk * D_ + tid] = v;
    }
    if (tid == 0) {
        float dn = 0.f;
        #pragma unroll
        for (int k = 0; k < 8; k++) dn += s_den[k];
        g_denF[blk] = dn;
    }
}

// ---------------------------------------------------------------------------
// k_F2: u2 = u1 + reduce16(hop-1 partials); hop-2 pass (C2 -> logit2 -> OUT,
// C3 -> num); last-arriving block per batch -> final u3 -> OUT.
// ---------------------------------------------------------------------------
__global__ void __launch_bounds__(256) k_F2(float* __restrict__ out)
{
    __shared__ __align__(16) float s_u[D_];
    __shared__ __align__(16) float s_n[2][D_];
    __shared__ float s_dn[2];
    __shared__ __align__(16) float s_pt[8][D_];
    __shared__ float s_den[8];
    __shared__ int s_last;

    const int blk  = blockIdx.x;
    const int b    = blk / FSPL;
    const int sp   = blk % FSPL;
    const int tid  = threadIdx.x;
    const int lane = tid & 31;
    const int wid  = tid >> 5;

    {
        const int dim  = tid & 127;
        const int half = tid >> 7;
        const int k0   = half * 8;
        float dn = 0.f, num = 0.f;
        #pragma unroll
        for (int k = k0; k < k0 + 8; k++) {
            dn  += g_denF[b * FSPL + k];
            num += g_partF[((size_t)b * FSPL + k) * D_ + dim];
        }
        s_n[half][dim] = num;
        if (dim == 0) s_dn[half] = dn;
    }
    __syncthreads();
    if (tid < D_) {
        s_u[tid] = g_u[(size_t)b * D_ + tid]
                 + (s_n[0][tid] + s_n[1][tid]) / (s_dn[0] + s_dn[1]);
    }
    __syncthreads();

    const float4 u4 = reinterpret_cast<const float4*>(s_u)[lane];
    const size_t bstr  = (size_t)B_ * M_ * (D_ / 4);
    const size_t rbase = (size_t)(b * M_ + sp * 32) * (D_ / 4) + lane;

    float4 acc = make_float4(0.f, 0.f, 0.f, 0.f);
    float den = 0.f;
    #pragma unroll
    for (int i = 0; i < 4; i++) {
        const int ml = wid * 4 + i;
        const size_t r = rbase + (size_t)ml * (D_ / 4);
        const float4 va = unpack4(g_bagh[bstr + r]);        // C2
        const float4 vb = unpack4(g_bagh[2 * bstr + r]);    // C3
        float d = va.x * u4.x + va.y * u4.y + va.z * u4.z + va.w * u4.w;
        d = warpSum(d);
        const float e = __expf(d);
        if (lane == 0) out[(size_t)b * M_ + sp * 32 + ml] = d;  // prob_logit
        acc.x += e * vb.x; acc.y += e * vb.y;
        acc.z += e * vb.z; acc.w += e * vb.w;
        den += e;
    }
    reinterpret_cast<float4*>(&s_pt[wid][0])[lane] = acc;
    if (lane == 0) s_den[wid] = den;
    __syncthreads();

    if (tid < D_) {
        float v = 0.f;
        #pragma unroll
        for (int k = 0; k < 8; k++) v += s_pt[k][tid];
        g_partF[(size_t)blk * D_ + tid] = v;     // reuse partF for hop-2
    }
    if (tid == 0) {
        float dn = 0.f;
        #pragma unroll
        for (int k = 0; k < 8; k++) dn += s_den[k];
        g_denF[blk] = dn;
    }
    __syncthreads();

    if (tid == 0) {
        __threadfence();
        const unsigned old = atomicAdd(&g_cnt[b], 1u);
        s_last = (old == FSPL - 1);
    }
    __syncthreads();
    if (s_last) {
        __threadfence();
        if (tid < D_) {
            float dn = 0.f;
            #pragma unroll
            for (int k = 0; k < FSPL; k++) dn += g_denF[b * FSPL + k];
            float num = 0.f;
            #pragma unroll
            for (int k = 0; k < FSPL; k++) num += g_partF[((size_t)b * FSPL + k) * D_ + tid];
            out[(size_t)B_ * M_ + (size_t)b * D_ + tid] = s_u[tid] + num / dn;
        }
        if (tid == 0) g_cnt[b] = 0;   // reset for next replay
    }
}

extern "C" void kernel_launch(void* const* d_in, const int* in_sizes, int n_in,
                              void* d_out, int out_size)
{
    const int*   story  = (const int*)  d_in[0];   // [B, M, S] int32
    const float* hidden = (const float*)d_in[1];   // [B, 1, D] f32
    const float* C      = (const float*)d_in[2];   // [4, V, D] f32
    float* out = (float*)d_out;                    // [B*M] logits ++ [B*D] u

    kA   <<<GA_BLKS + GE_BLKS, 256>>>(story, hidden, C);  // gather C1..C3 + dot0 GEMM
    k_F0 <<<FBLK, 256>>>(story);                          // hop-0 body -> partials
    k_F1 <<<FBLK, 256>>>(hidden);                         // u1 + hop-1 pass
    k_F2 <<<FBLK, 256>>>(out);                            // u2 + hop-2 + final u3
}

// round 11
// speedup vs baseline: 1.3625x; 1.3625x over previous
#include <cuda_runtime.h>
#include <cuda_fp16.h>
#include <cstdint>

#define B_    32
#define M_    512
#define S_    10
#define V_    32000
#define D_    128

#define GBLK  2048            // gather blocks: 512 thr, 8 m per block, 2 warps/m
#define GPB   64              // gather blocks per batch (hop-0 partials per batch)
#define GE_BLKS 500           // GEMM blocks
#define GE_ROWS 64            // C0 rows per GEMM block (8 warps x 8 rows)
#define FSPL  16              // m-splits per batch in k_F -> 512 blocks
#define FBLK  (B_ * FSPL)

// Bags for tables 1..3 in fp16, packed 4 dims per uint2.
__device__ __align__(16) uint2 g_bagh[3u * B_ * M_ * (D_ / 4)];   // 12.6 MB
__device__ __align__(16) float g_dot0[V_ * B_];        // dot0[v][b] = C0[v]·u0[b] (4 MB)
__device__ __align__(16) float g_part0[GBLK * D_];     // hop-0 partials (gather)
__device__ float g_den0[GBLK];
__device__ __align__(16) float g_partF[FBLK * D_];     // hop partials (k_F1/k_F2)
__device__ float g_denF[FBLK];
__device__ __align__(16) float g_u[B_ * D_];           // u1 (published by k_F1)
__device__ unsigned int g_cnt[B_];                     // k_F2 arrival counters (self-reset)

__device__ __forceinline__ float warpSum(float v) {
    #pragma unroll
    for (int o = 16; o > 0; o >>= 1) v += __shfl_xor_sync(0xffffffffu, v, o);
    return v;
}
__device__ __forceinline__ uint2 pack4(float4 v) {
    __half2 lo = __floats2half2_rn(v.x, v.y);
    __half2 hi = __floats2half2_rn(v.z, v.w);
    uint2 r;
    r.x = *reinterpret_cast<unsigned*>(&lo);
    r.y = *reinterpret_cast<unsigned*>(&hi);
    return r;
}
__device__ __forceinline__ float4 unpack4(uint2 p) {
    __half2 lo = *reinterpret_cast<__half2*>(&p.x);
    __half2 hi = *reinterpret_cast<__half2*>(&p.y);
    float2 l = __half22float2(lo);
    float2 h = __half22float2(hi);
    return make_float4(l.x, l.y, h.x, h.y);
}

// ---------------------------------------------------------------------------
// k_gemm: dot0[v][b] = C0[v]·u0[b]. Sequential C0 reads (16.4 MB once).
// 500 blocks x 256 thr; 8 warps x 8 rows per block, 4 rows per stage.
// ---------------------------------------------------------------------------
__global__ void __launch_bounds__(256) k_gemm(const float* __restrict__ hidden,
                                              const float* __restrict__ C)
{
    __shared__ __align__(16) float4 s_stage[8][4][32];   // 8 warps x 4 rows x 128 dims
    __shared__ __align__(16) float4 s_u0[32][33];        // [d4][b], padded

    const int tid  = threadIdx.x;
    const int lane = tid & 31;
    const int wid  = tid >> 5;
    const float4* C4 = reinterpret_cast<const float4*>(C);

    for (int i = tid; i < 32 * 32; i += 256) {
        const int d4 = i >> 5, b = i & 31;
        s_u0[d4][b] = reinterpret_cast<const float4*>(hidden)[(size_t)b * 32 + d4];
    }
    __syncthreads();

    const int vwarp = blockIdx.x * GE_ROWS + wid * (GE_ROWS / 8);
    #pragma unroll
    for (int it = 0; it < (GE_ROWS / 8) / 4; it++) {     // 2 iters of 4 rows
        const int v0 = vwarp + it * 4;
        #pragma unroll
        for (int k = 0; k < 4; k++)
            s_stage[wid][k][lane] = C4[(size_t)(v0 + k) * 32 + lane];   // C0 rows
        __syncwarp();
        float acc0 = 0.f, acc1 = 0.f, acc2 = 0.f, acc3 = 0.f;
        #pragma unroll
        for (int d4 = 0; d4 < 32; d4++) {
            const float4 u = s_u0[d4][lane];           // lane = batch b
            const float4 r0 = s_stage[wid][0][d4];
            const float4 r1 = s_stage[wid][1][d4];
            const float4 r2 = s_stage[wid][2][d4];
            const float4 r3 = s_stage[wid][3][d4];
            acc0 += r0.x * u.x + r0.y * u.y + r0.z * u.z + r0.w * u.w;
            acc1 += r1.x * u.x + r1.y * u.y + r1.z * u.z + r1.w * u.w;
            acc2 += r2.x * u.x + r2.y * u.y + r2.z * u.z + r2.w * u.w;
            acc3 += r3.x * u.x + r3.y * u.y + r3.z * u.z + r3.w * u.w;
        }
        __syncwarp();
        g_dot0[(size_t)(v0 + 0) * B_ + lane] = acc0;
        g_dot0[(size_t)(v0 + 1) * B_ + lane] = acc1;
        g_dot0[(size_t)(v0 + 2) * B_ + lane] = acc2;
        g_dot0[(size_t)(v0 + 3) * B_ + lane] = acc3;
    }
}

// ---------------------------------------------------------------------------
// k_gather (R8 shape): TWO warps per (b,m).
// X-warp (wid 0..7): table C1 accumulate + hop-0 body (logit0 from g_dot0,
//   exp, partial e*bagC1) + bagC1 store.
// Y-warp (wid 8..15): tables C2,C3 accumulate + stores.
// No C0 table traffic. __launch_bounds__(512,3) -> 48 warps/SM.
// ---------------------------------------------------------------------------
__global__ void __launch_bounds__(512, 3) k_gather(const int* __restrict__ story,
                                                   const float* __restrict__ C)
{
    __shared__ __align__(16) float s_pt[8][D_];
    __shared__ float s_den[8];

    const int tid  = threadIdx.x;
    const int lane = tid & 31;
    const int wid  = tid >> 5;          // 0..15
    const bool isX = (wid < 8);
    const int  ml  = wid & 7;
    const int  g   = blockIdx.x * 8 + ml;
    const int  b   = g >> 9;
    const int  m   = g & (M_ - 1);

    int tok = 0;
    if (lane < S_) tok = story[((size_t)b * M_ + m) * S_ + lane];

    const float4* C4 = reinterpret_cast<const float4*>(C);
    const size_t tabstr = (size_t)V_ * (D_ / 4);
    const size_t row  = ((size_t)b * M_ + m) * (D_ / 4) + lane;
    const size_t bstr = (size_t)B_ * M_ * (D_ / 4);

    if (isX) {
        // ---- table C1 + hop-0 body ----
        float4 a1 = make_float4(0.f, 0.f, 0.f, 0.f);
        float dl = 0.f;
        if (lane < S_) dl = g_dot0[(size_t)tok * B_ + b];   // dot0[tok][b]
        #pragma unroll
        for (int s = 0; s < S_; s++) {
            const int t = __shfl_sync(0xffffffffu, tok, s);
            const float4 r1 = C4[(size_t)t * (D_ / 4) + lane + tabstr];
            a1.x += r1.x; a1.y += r1.y; a1.z += r1.z; a1.w += r1.w;
        }
        const float logit0 = warpSum(dl);
        const float e = __expf(logit0);
        reinterpret_cast<float4*>(&s_pt[ml][0])[lane] =
            make_float4(e * a1.x, e * a1.y, e * a1.z, e * a1.w);
        if (lane == 0) s_den[ml] = e;
        g_bagh[row] = pack4(a1);                 // table C1
    } else {
        // ---- tables C2, C3 ----
        float4 a2 = make_float4(0.f, 0.f, 0.f, 0.f);
        float4 a3 = a2;
        #pragma unroll
        for (int s = 0; s < S_; s++) {
            const int t = __shfl_sync(0xffffffffu, tok, s);
            const size_t idx = (size_t)t * (D_ / 4) + lane;
            const float4 r2 = C4[idx + 2 * tabstr];
            const float4 r3 = C4[idx + 3 * tabstr];
            a2.x += r2.x; a2.y += r2.y; a2.z += r2.z; a2.w += r2.w;
            a3.x += r3.x; a3.y += r3.y; a3.z += r3.z; a3.w += r3.w;
        }
        g_bagh[row + bstr]     = pack4(a2);      // table C2
        g_bagh[row + 2 * bstr] = pack4(a3);      // table C3
    }

    __syncthreads();
    if (tid < D_) {
        float v = 0.f;
        #pragma unroll
        for (int k = 0; k < 8; k++) v += s_pt[k][tid];
        g_part0[(size_t)blockIdx.x * D_ + tid] = v;
    }
    if (tid == 0) {
        float dn = 0.f;
        #pragma unroll
        for (int k = 0; k < 8; k++) dn += s_den[k];
        g_den0[blockIdx.x] = dn;
    }
}

// ---------------------------------------------------------------------------
// k_F1 (R8-identical): u1 = hidden + reduce64(hop-0 partials) [redundant,
// 2-level]; hop-1 pass (C1 -> logit, C2 -> num); sp==0 publishes u1.
// ---------------------------------------------------------------------------
__global__ void __launch_bounds__(256) k_F1(const float* __restrict__ hidden)
{
    __shared__ __align__(16) float s_u[D_];
    __shared__ __align__(16) float s_n[2][D_];
    __shared__ float s_dn[2];
    __shared__ __align__(16) float s_pt[8][D_];
    __shared__ float s_den[8];

    const int blk  = blockIdx.x;
    const int b    = blk / FSPL;
    const int sp   = blk % FSPL;
    const int tid  = threadIdx.x;
    const int lane = tid & 31;
    const int wid  = tid >> 5;

    {
        const int dim  = tid & 127;
        const int half = tid >> 7;
        const int k0   = half * 32;
        float dn = 0.f, num = 0.f;
        #pragma unroll 8
        for (int k = k0; k < k0 + 32; k++) {
            dn  += g_den0[b * GPB + k];
            num += g_part0[((size_t)b * GPB + k) * D_ + dim];
        }
        s_n[half][dim] = num;
        if (dim == 0) s_dn[half] = dn;
    }
    __syncthreads();
    if (tid < D_) {
        s_u[tid] = hidden[(size_t)b * D_ + tid]
                 + (s_n[0][tid] + s_n[1][tid]) / (s_dn[0] + s_dn[1]);
        if (sp == 0) g_u[(size_t)b * D_ + tid] = s_u[tid];
    }
    __syncthreads();

    const float4 u4 = reinterpret_cast<const float4*>(s_u)[lane];
    const size_t bstr  = (size_t)B_ * M_ * (D_ / 4);
    const size_t rbase = (size_t)(b * M_ + sp * 32) * (D_ / 4) + lane;

    float4 acc = make_float4(0.f, 0.f, 0.f, 0.f);
    float den = 0.f;
    #pragma unroll
    for (int i = 0; i < 4; i++) {
        const int ml = wid * 4 + i;
        const size_t r = rbase + (size_t)ml * (D_ / 4);
        const float4 va = unpack4(g_bagh[r]);               // C1
        const float4 vb = unpack4(g_bagh[bstr + r]);        // C2
        float d = va.x * u4.x + va.y * u4.y + va.z * u4.z + va.w * u4.w;
        d = warpSum(d);
        const float e = __expf(d);
        acc.x += e * vb.x; acc.y += e * vb.y;
        acc.z += e * vb.z; acc.w += e * vb.w;
        den += e;
    }
    reinterpret_cast<float4*>(&s_pt[wid][0])[lane] = acc;
    if (lane == 0) s_den[wid] = den;
    __syncthreads();

    if (tid < D_) {
        float v = 0.f;
        #pragma unroll
        for (int k = 0; k < 8; k++) v += s_pt[k][tid];
        g_partF[(size_t)blk * D_ + tid] = v;
    }
    if (tid == 0) {
        float dn = 0.f;
        #pragma unroll
        for (int k = 0; k < 8; k++) dn += s_den[k];
        g_denF[blk] = dn;
    }
}

// ---------------------------------------------------------------------------
// k_F2 (R8-identical): u2 = u1 + reduce16(hop-1 partials); hop-2 pass
// (logits -> OUT); last-arriving block per batch -> final u3 -> OUT.
// ---------------------------------------------------------------------------
__global__ void __launch_bounds__(256) k_F2(float* __restrict__ out)
{
    __shared__ __align__(16) float s_u[D_];
    __shared__ __align__(16) float s_n[2][D_];
    __shared__ float s_dn[2];
    __shared__ __align__(16) float s_pt[8][D_];
    __shared__ float s_den[8];
    __shared__ int s_last;

    const int blk  = blockIdx.x;
    const int b    = blk / FSPL;
    const int sp   = blk % FSPL;
    const int tid  = threadIdx.x;
    const int lane = tid & 31;
    const int wid  = tid >> 5;

    {
        const int dim  = tid & 127;
        const int half = tid >> 7;
        const int k0   = half * 8;
        float dn = 0.f, num = 0.f;
        #pragma unroll
        for (int k = k0; k < k0 + 8; k++) {
            dn  += g_denF[b * FSPL + k];
            num += g_partF[((size_t)b * FSPL + k) * D_ + dim];
        }
        s_n[half][dim] = num;
        if (dim == 0) s_dn[half] = dn;
    }
    __syncthreads();
    if (tid < D_) {
        s_u[tid] = g_u[(size_t)b * D_ + tid]
                 + (s_n[0][tid] + s_n[1][tid]) / (s_dn[0] + s_dn[1]);
    }
    __syncthreads();

    const float4 u4 = reinterpret_cast<const float4*>(s_u)[lane];
    const size_t bstr  = (size_t)B_ * M_ * (D_ / 4);
    const size_t rbase = (size_t)(b * M_ + sp * 32) * (D_ / 4) + lane;

    float4 acc = make_float4(0.f, 0.f, 0.f, 0.f);
    float den = 0.f;
    #pragma unroll
    for (int i = 0; i < 4; i++) {
        const int ml = wid * 4 + i;
        const size_t r = rbase + (size_t)ml * (D_ / 4);
        const float4 va = unpack4(g_bagh[bstr + r]);        // C2
        const float4 vb = unpack4(g_bagh[2 * bstr + r]);    // C3
        float d = va.x * u4.x + va.y * u4.y + va.z * u4.z + va.w * u4.w;
        d = warpSum(d);
        const float e = __expf(d);
        if (lane == 0) out[(size_t)b * M_ + sp * 32 + ml] = d;  // prob_logit
        acc.x += e * vb.x; acc.y += e * vb.y;
        acc.z += e * vb.z; acc.w += e * vb.w;
        den += e;
    }
    reinterpret_cast<float4*>(&s_pt[wid][0])[lane] = acc;
    if (lane == 0) s_den[wid] = den;
    __syncthreads();

    if (tid < D_) {
        float v = 0.f;
        #pragma unroll
        for (int k = 0; k < 8; k++) v += s_pt[k][tid];
        g_partF[(size_t)blk * D_ + tid] = v;     // reuse partF for hop-2
    }
    if (tid == 0) {
        float dn = 0.f;
        #pragma unroll
        for (int k = 0; k < 8; k++) dn += s_den[k];
        g_denF[blk] = dn;
    }
    __syncthreads();

    if (tid == 0) {
        __threadfence();
        const unsigned old = atomicAdd(&g_cnt[b], 1u);
        s_last = (old == FSPL - 1);
    }
    __syncthreads();
    if (s_last) {
        __threadfence();
        if (tid < D_) {
            float dn = 0.f;
            #pragma unroll
            for (int k = 0; k < FSPL; k++) dn += g_denF[b * FSPL + k];
            float num = 0.f;
            #pragma unroll
            for (int k = 0; k < FSPL; k++) num += g_partF[((size_t)b * FSPL + k) * D_ + tid];
            out[(size_t)B_ * M_ + (size_t)b * D_ + tid] = s_u[tid] + num / dn;
        }
        if (tid == 0) g_cnt[b] = 0;   // reset for next replay
    }
}

extern "C" void kernel_launch(void* const* d_in, const int* in_sizes, int n_in,
                              void* d_out, int out_size)
{
    const int*   story  = (const int*)  d_in[0];   // [B, M, S] int32
    const float* hidden = (const float*)d_in[1];   // [B, 1, D] f32
    const float* C      = (const float*)d_in[2];   // [4, V, D] f32
    float* out = (float*)d_out;                    // [B*M] logits ++ [B*D] u

    k_gemm  <<<GE_BLKS, 256>>>(hidden, C);         // dot0 = C0 x u0
    k_gather<<<GBLK, 512>>>(story, C);             // C1..C3 bags + hop-0 fused
    k_F1    <<<FBLK, 256>>>(hidden);               // u1 + hop-1 pass
    k_F2    <<<FBLK, 256>>>(out);                  // u2 + hop-2 + final u3
}

// round 12
// speedup vs baseline: 1.9000x; 1.3945x over previous
#include <cuda_runtime.h>
#include <cuda_fp16.h>
#include <cstdint>

#define B_    32
#define M_    512
#define S_    10
#define V_    32000
#define D_    128

#define GBLK  2048            // gather blocks: 512 thr, 8 m per block, 2 warps/m
#define GPB   64              // gather blocks per batch (hop-0 partials per batch)
#define FSPL  16              // m-splits per batch in k_F -> 512 blocks, 32 m/block
#define FBLK  (B_ * FSPL)

// Bags for tables 1..3 in fp16, packed 4 dims per uint2.
__device__ __align__(16) uint2 g_bagh[3u * B_ * M_ * (D_ / 4)];   // 12.6 MB
__device__ __align__(16) float g_part0[GBLK * D_];     // hop-0 partials (gather)
__device__ float g_den0[GBLK];
__device__ __align__(16) float g_partF[FBLK * D_];     // hop partials (k_F1/k_F2)
__device__ float g_denF[FBLK];
__device__ __align__(16) float g_u[B_ * D_];           // u1 (published by k_F1)
__device__ unsigned int g_cnt[B_];                     // k_F2 arrival counters (self-reset)

__device__ __forceinline__ float warpSum(float v) {
    #pragma unroll
    for (int o = 16; o > 0; o >>= 1) v += __shfl_xor_sync(0xffffffffu, v, o);
    return v;
}
__device__ __forceinline__ uint2 pack4(float4 v) {
    __half2 lo = __floats2half2_rn(v.x, v.y);
    __half2 hi = __floats2half2_rn(v.z, v.w);
    uint2 r;
    r.x = *reinterpret_cast<unsigned*>(&lo);
    r.y = *reinterpret_cast<unsigned*>(&hi);
    return r;
}
__device__ __forceinline__ float4 unpack4(uint2 p) {
    __half2 lo = *reinterpret_cast<__half2*>(&p.x);
    __half2 hi = *reinterpret_cast<__half2*>(&p.y);
    float2 l = __half22float2(lo);
    float2 h = __half22float2(hi);
    return make_float4(l.x, l.y, h.x, h.y);
}

// ---------------------------------------------------------------------------
// Gather (R8-identical, proven): TWO warps per (b,m).
// X-warp (wid 0..7): tables C0,C1 — hop-0 dot, exp, partial, bag-C1 store.
// Y-warp (wid 8..15): tables C2,C3 bag stores.
// __launch_bounds__(512,3) -> 48 warps/SM (75% occ).
// ---------------------------------------------------------------------------
__global__ void __launch_bounds__(512, 3) k_gather(const int* __restrict__ story,
                                                   const float* __restrict__ hidden,
                                                   const float* __restrict__ C)
{
    __shared__ __align__(16) float s_pt[8][D_];
    __shared__ float s_den[8];

    const int tid  = threadIdx.x;
    const int lane = tid & 31;
    const int wid  = tid >> 5;          // 0..15
    const bool isX = (wid < 8);
    const int  ml  = wid & 7;           // m-local 0..7
    const int  g   = blockIdx.x * 8 + ml;
    const int  b   = g >> 9;            // / M_
    const int  m   = g & (M_ - 1);

    int tok = 0;
    if (lane < S_) tok = story[((size_t)b * M_ + m) * S_ + lane];

    const float4* C4 = reinterpret_cast<const float4*>(C);
    const size_t tabstr = (size_t)V_ * (D_ / 4);
    const float4* base0 = C4 + (isX ? 0 : 2) * tabstr;   // C0 or C2

    float4 a0 = make_float4(0.f, 0.f, 0.f, 0.f);
    float4 a1 = a0;

    #pragma unroll
    for (int s = 0; s < S_; s++) {
        const int t = __shfl_sync(0xffffffffu, tok, s);
        const size_t idx = (size_t)t * (D_ / 4) + lane;
        const float4 r0 = base0[idx];
        const float4 r1 = base0[idx + tabstr];
        a0.x += r0.x; a0.y += r0.y; a0.z += r0.z; a0.w += r0.w;
        a1.x += r1.x; a1.y += r1.y; a1.z += r1.z; a1.w += r1.w;
    }

    const size_t row  = ((size_t)b * M_ + m) * (D_ / 4) + lane;
    const size_t bstr = (size_t)B_ * M_ * (D_ / 4);

    if (isX) {
        const float4 u4 = reinterpret_cast<const float4*>(hidden + (size_t)b * D_)[lane];
        float d = a0.x * u4.x + a0.y * u4.y + a0.z * u4.z + a0.w * u4.w;
        d = warpSum(d);
        const float e = __expf(d);
        reinterpret_cast<float4*>(&s_pt[ml][0])[lane] =
            make_float4(e * a1.x, e * a1.y, e * a1.z, e * a1.w);
        if (lane == 0) s_den[ml] = e;
        g_bagh[row] = pack4(a1);                 // table C1
    } else {
        g_bagh[row + bstr]     = pack4(a0);      // table C2
        g_bagh[row + 2 * bstr] = pack4(a1);      // table C3
    }

    __syncthreads();
    if (tid < D_) {
        float v = 0.f;
        #pragma unroll
        for (int k = 0; k < 8; k++) v += s_pt[k][tid];
        g_part0[(size_t)blockIdx.x * D_ + tid] = v;
    }
    if (tid == 0) {
        float dn = 0.f;
        #pragma unroll
        for (int k = 0; k < 8; k++) dn += s_den[k];
        g_den0[blockIdx.x] = dn;
    }
}

// ---------------------------------------------------------------------------
// k_F1: u1 = hidden + reduce64(hop-0 partials) [redundant, 2-level];
// hop-1 pass with ALL bag loads prefetched (MLP 8); sp==0 publishes u1.
// ---------------------------------------------------------------------------
__global__ void __launch_bounds__(256) k_F1(const float* __restrict__ hidden)
{
    __shared__ __align__(16) float s_u[D_];
    __shared__ __align__(16) float s_n[2][D_];
    __shared__ float s_dn[2];
    __shared__ __align__(16) float s_pt[8][D_];
    __shared__ float s_den[8];

    const int blk  = blockIdx.x;
    const int b    = blk / FSPL;
    const int sp   = blk % FSPL;
    const int tid  = threadIdx.x;
    const int lane = tid & 31;
    const int wid  = tid >> 5;

    const size_t bstr  = (size_t)B_ * M_ * (D_ / 4);
    const size_t rbase = (size_t)(b * M_ + sp * 32) * (D_ / 4) + lane;

    // Prefetch all 8 bag rows for this warp (issued before the reduce below,
    // so their latency overlaps the partial-reduce work).
    uint2 ra[4], rb[4];
    #pragma unroll
    for (int i = 0; i < 4; i++) {
        const size_t r = rbase + (size_t)(wid * 4 + i) * (D_ / 4);
        ra[i] = g_bagh[r];               // C1
        rb[i] = g_bagh[bstr + r];        // C2
    }

    // ---- u1 reduce (2-level: 2 threads per dim x 32 partials) ----
    {
        const int dim  = tid & 127;
        const int half = tid >> 7;
        const int k0   = half * 32;
        float dn = 0.f, num = 0.f;
        #pragma unroll 8
        for (int k = k0; k < k0 + 32; k++) {
            dn  += g_den0[b * GPB + k];
            num += g_part0[((size_t)b * GPB + k) * D_ + dim];
        }
        s_n[half][dim] = num;
        if (dim == 0) s_dn[half] = dn;
    }
    __syncthreads();
    if (tid < D_) {
        s_u[tid] = hidden[(size_t)b * D_ + tid]
                 + (s_n[0][tid] + s_n[1][tid]) / (s_dn[0] + s_dn[1]);
        if (sp == 0) g_u[(size_t)b * D_ + tid] = s_u[tid];
    }
    __syncthreads();

    // ---- hop-1 pass on prefetched rows ----
    const float4 u4 = reinterpret_cast<const float4*>(s_u)[lane];
    float4 acc = make_float4(0.f, 0.f, 0.f, 0.f);
    float den = 0.f;
    #pragma unroll
    for (int i = 0; i < 4; i++) {
        const float4 va = unpack4(ra[i]);
        const float4 vb = unpack4(rb[i]);
        float d = va.x * u4.x + va.y * u4.y + va.z * u4.z + va.w * u4.w;
        d = warpSum(d);
        const float e = __expf(d);
        acc.x += e * vb.x; acc.y += e * vb.y;
        acc.z += e * vb.z; acc.w += e * vb.w;
        den += e;
    }
    reinterpret_cast<float4*>(&s_pt[wid][0])[lane] = acc;
    if (lane == 0) s_den[wid] = den;
    __syncthreads();

    if (tid < D_) {
        float v = 0.f;
        #pragma unroll
        for (int k = 0; k < 8; k++) v += s_pt[k][tid];
        g_partF[(size_t)blk * D_ + tid] = v;
    }
    if (tid == 0) {
        float dn = 0.f;
        #pragma unroll
        for (int k = 0; k < 8; k++) dn += s_den[k];
        g_denF[blk] = dn;
    }
}

// ---------------------------------------------------------------------------
// k_F2: u2 = u1 + reduce16(hop-1 partials); hop-2 pass with prefetched loads
// (logits -> OUT); last-arriving block per batch -> final u3 -> OUT.
// ---------------------------------------------------------------------------
__global__ void __launch_bounds__(256) k_F2(float* __restrict__ out)
{
    __shared__ __align__(16) float s_u[D_];
    __shared__ __align__(16) float s_n[2][D_];
    __shared__ float s_dn[2];
    __shared__ __align__(16) float s_pt[8][D_];
    __shared__ float s_den[8];
    __shared__ int s_last;

    const int blk  = blockIdx.x;
    const int b    = blk / FSPL;
    const int sp   = blk % FSPL;
    const int tid  = threadIdx.x;
    const int lane = tid & 31;
    const int wid  = tid >> 5;

    const size_t bstr  = (size_t)B_ * M_ * (D_ / 4);
    const size_t rbase = (size_t)(b * M_ + sp * 32) * (D_ / 4) + lane;

    // Prefetch all 8 bag rows (C2 for logits, C3 for combine).
    uint2 ra[4], rb[4];
    #pragma unroll
    for (int i = 0; i < 4; i++) {
        const size_t r = rbase + (size_t)(wid * 4 + i) * (D_ / 4);
        ra[i] = g_bagh[bstr + r];        // C2
        rb[i] = g_bagh[2 * bstr + r];    // C3
    }

    // ---- u2 reduce (2-level: 2 threads per dim x 8 partials) ----
    {
        const int dim  = tid & 127;
        const int half = tid >> 7;
        const int k0   = half * 8;
        float dn = 0.f, num = 0.f;
        #pragma unroll
        for (int k = k0; k < k0 + 8; k++) {
            dn  += g_denF[b * FSPL + k];
            num += g_partF[((size_t)b * FSPL + k) * D_ + dim];
        }
        s_n[half][dim] = num;
        if (dim == 0) s_dn[half] = dn;
    }
    __syncthreads();
    if (tid < D_) {
        s_u[tid] = g_u[(size_t)b * D_ + tid]
                 + (s_n[0][tid] + s_n[1][tid]) / (s_dn[0] + s_dn[1]);
    }
    __syncthreads();

    // ---- hop-2 pass on prefetched rows: logits -> OUT; partials for u3 ----
    const float4 u4 = reinterpret_cast<const float4*>(s_u)[lane];
    float4 acc = make_float4(0.f, 0.f, 0.f, 0.f);
    float den = 0.f;
    #pragma unroll
    for (int i = 0; i < 4; i++) {
        const float4 va = unpack4(ra[i]);
        const float4 vb = unpack4(rb[i]);
        float d = va.x * u4.x + va.y * u4.y + va.z * u4.z + va.w * u4.w;
        d = warpSum(d);
        const float e = __expf(d);
        if (lane == 0) out[(size_t)b * M_ + sp * 32 + wid * 4 + i] = d;  // prob_logit
        acc.x += e * vb.x; acc.y += e * vb.y;
        acc.z += e * vb.z; acc.w += e * vb.w;
        den += e;
    }
    reinterpret_cast<float4*>(&s_pt[wid][0])[lane] = acc;
    if (lane == 0) s_den[wid] = den;
    __syncthreads();

    if (tid < D_) {
        float v = 0.f;
        #pragma unroll
        for (int k = 0; k < 8; k++) v += s_pt[k][tid];
        g_partF[(size_t)blk * D_ + tid] = v;     // reuse partF for hop-2
    }
    if (tid == 0) {
        float dn = 0.f;
        #pragma unroll
        for (int k = 0; k < 8; k++) dn += s_den[k];
        g_denF[blk] = dn;
    }
    __syncthreads();

    if (tid == 0) {
        __threadfence();
        const unsigned old = atomicAdd(&g_cnt[b], 1u);
        s_last = (old == FSPL - 1);
    }
    __syncthreads();
    if (s_last) {
        __threadfence();   // acquire peers' partial writes
        if (tid < D_) {
            float dn = 0.f;
            #pragma unroll
            for (int k = 0; k < FSPL; k++) dn += g_denF[b * FSPL + k];
            float num = 0.f;
            #pragma unroll
            for (int k = 0; k < FSPL; k++) num += g_partF[((size_t)b * FSPL + k) * D_ + tid];
            out[(size_t)B_ * M_ + (size_t)b * D_ + tid] = s_u[tid] + num / dn;
        }
        if (tid == 0) g_cnt[b] = 0;   // reset for next replay
    }
}

extern "C" void kernel_launch(void* const* d_in, const int* in_sizes, int n_in,
                              void* d_out, int out_size)
{
    const int*   story  = (const int*)  d_in[0];   // [B, M, S] int32
    const float* hidden = (const float*)d_in[1];   // [B, 1, D] f32
    const float* C      = (const float*)d_in[2];   // [4, V, D] f32
    float* out = (float*)d_out;                    // [B*M] logits ++ [B*D] u

    k_gather<<<GBLK, 512>>>(story, hidden, C);     // hop-0 fused, 2 warps/(b,m)
    k_F1    <<<FBLK, 256>>>(hidden);               // u1 + hop-1 pass
    k_F2    <<<FBLK, 256>>>(out);                  // u2 + hop-2 + final u3
}

// round 13
// speedup vs baseline: 2.0000x; 1.0526x over previous
#include <cuda_runtime.h>
#include <cuda_fp16.h>
#include <cstdint>

#define B_    32
#define M_    512
#define S_    10
#define V_    32000
#define D_    128

#define GBLK  2048            // gather blocks: 512 thr, 8 m per block, 2 warps/m
#define GPB   64              // gather blocks per batch (hop-0 partials per batch)
#define FSPL  16              // m-splits per batch in k_F -> 512 blocks, 32 m/block
#define FBLK  (B_ * FSPL)

// Bags for tables 1..3 in fp16, packed 4 dims per uint2.
__device__ __align__(16) uint2 g_bagh[3u * B_ * M_ * (D_ / 4)];   // 12.6 MB
__device__ __align__(16) float g_part0[GBLK * D_];     // hop-0 partials (gather)
__device__ float g_den0[GBLK];
__device__ __align__(16) float g_part1[FBLK * D_];     // hop-1 partials
__device__ float g_den1[FBLK];
__device__ __align__(16) float g_part2[FBLK * D_];     // hop-2 partials
__device__ float g_den2[FBLK];
__device__ unsigned int g_cA[B_];    // per-batch monotonic tickets (never reset)
__device__ unsigned int g_cB[B_];

__device__ __forceinline__ float warpSum(float v) {
    #pragma unroll
    for (int o = 16; o > 0; o >>= 1) v += __shfl_xor_sync(0xffffffffu, v, o);
    return v;
}
__device__ __forceinline__ uint2 pack4(float4 v) {
    __half2 lo = __floats2half2_rn(v.x, v.y);
    __half2 hi = __floats2half2_rn(v.z, v.w);
    uint2 r;
    r.x = *reinterpret_cast<unsigned*>(&lo);
    r.y = *reinterpret_cast<unsigned*>(&hi);
    return r;
}
__device__ __forceinline__ float4 unpack4(uint2 p) {
    __half2 lo = *reinterpret_cast<__half2*>(&p.x);
    __half2 hi = *reinterpret_cast<__half2*>(&p.y);
    float2 l = __half22float2(lo);
    float2 h = __half22float2(hi);
    return make_float4(l.x, l.y, h.x, h.y);
}

// ---------------------------------------------------------------------------
// Gather (R8-identical, at the LTS/L1tex floor): TWO warps per (b,m).
// X-warp (wid 0..7): tables C0,C1 — hop-0 dot, exp, partial, bag-C1 store.
// Y-warp (wid 8..15): tables C2,C3 bag stores.
// ---------------------------------------------------------------------------
__global__ void __launch_bounds__(512, 3) k_gather(const int* __restrict__ story,
                                                   const float* __restrict__ hidden,
                                                   const float* __restrict__ C)
{
    __shared__ __align__(16) float s_pt[8][D_];
    __shared__ float s_den[8];

    const int tid  = threadIdx.x;
    const int lane = tid & 31;
    const int wid  = tid >> 5;          // 0..15
    const bool isX = (wid < 8);
    const int  ml  = wid & 7;           // m-local 0..7
    const int  g   = blockIdx.x * 8 + ml;
    const int  b   = g >> 9;            // / M_
    const int  m   = g & (M_ - 1);

    int tok = 0;
    if (lane < S_) tok = story[((size_t)b * M_ + m) * S_ + lane];

    const float4* C4 = reinterpret_cast<const float4*>(C);
    const size_t tabstr = (size_t)V_ * (D_ / 4);
    const float4* base0 = C4 + (isX ? 0 : 2) * tabstr;   // C0 or C2

    float4 a0 = make_float4(0.f, 0.f, 0.f, 0.f);
    float4 a1 = a0;

    #pragma unroll
    for (int s = 0; s < S_; s++) {
        const int t = __shfl_sync(0xffffffffu, tok, s);
        const size_t idx = (size_t)t * (D_ / 4) + lane;
        const float4 r0 = base0[idx];
        const float4 r1 = base0[idx + tabstr];
        a0.x += r0.x; a0.y += r0.y; a0.z += r0.z; a0.w += r0.w;
        a1.x += r1.x; a1.y += r1.y; a1.z += r1.z; a1.w += r1.w;
    }

    const size_t row  = ((size_t)b * M_ + m) * (D_ / 4) + lane;
    const size_t bstr = (size_t)B_ * M_ * (D_ / 4);

    if (isX) {
        const float4 u4 = reinterpret_cast<const float4*>(hidden + (size_t)b * D_)[lane];
        float d = a0.x * u4.x + a0.y * u4.y + a0.z * u4.z + a0.w * u4.w;
        d = warpSum(d);
        const float e = __expf(d);
        reinterpret_cast<float4*>(&s_pt[ml][0])[lane] =
            make_float4(e * a1.x, e * a1.y, e * a1.z, e * a1.w);
        if (lane == 0) s_den[ml] = e;
        g_bagh[row] = pack4(a1);                 // table C1
    } else {
        g_bagh[row + bstr]     = pack4(a0);      // table C2
        g_bagh[row + 2 * bstr] = pack4(a1);      // table C3
    }

    __syncthreads();
    if (tid < D_) {
        float v = 0.f;
        #pragma unroll
        for (int k = 0; k < 8; k++) v += s_pt[k][tid];
        g_part0[(size_t)blockIdx.x * D_ + tid] = v;
    }
    if (tid == 0) {
        float dn = 0.f;
        #pragma unroll
        for (int k = 0; k < 8; k++) dn += s_den[k];
        g_den0[blockIdx.x] = dn;
    }
}

// ---------------------------------------------------------------------------
// k_F: hops 1 AND 2 in one kernel; cross-block sync is PER-BATCH only
// (16 blocks), via monotonic tickets. Batches overlap freely.
//   Phase A: u1 = hidden + reduce64(part0)  [redundant/block]
//            hop-1 pass (C1 -> logit, C2 -> num) -> part1
//            batch-barrier A
//   Phase B: u2 = u1 + reduce16(part1)      [redundant/block; u1 from SMEM]
//            hop-2 pass (C2 -> logit -> OUT, C3 -> num) -> part2
//            last-arriver (mod-16) -> u3 -> OUT
// ---------------------------------------------------------------------------
__global__ void __launch_bounds__(256, 4) k_F(const float* __restrict__ hidden,
                                              float* __restrict__ out)
{
    __shared__ __align__(16) float s_u[D_];
    __shared__ __align__(16) float s_n[2][D_];
    __shared__ float s_dn[2];
    __shared__ __align__(16) float s_pt[8][D_];
    __shared__ float s_den[8];
    __shared__ int s_last;

    const int blk  = blockIdx.x;
    const int b    = blk / FSPL;
    const int sp   = blk % FSPL;
    const int tid  = threadIdx.x;
    const int lane = tid & 31;
    const int wid  = tid >> 5;

    const size_t bstr  = (size_t)B_ * M_ * (D_ / 4);
    const size_t rbase = (size_t)(b * M_ + sp * 32) * (D_ / 4) + lane;

    // Prefetch hop-1 rows (C1, C2): latency overlaps the u1 reduce.
    uint2 ra[4], rb[4];
    #pragma unroll
    for (int i = 0; i < 4; i++) {
        const size_t r = rbase + (size_t)(wid * 4 + i) * (D_ / 4);
        ra[i] = g_bagh[r];               // C1
        rb[i] = g_bagh[bstr + r];        // C2
    }

    // ---- Phase A: u1 reduce (2 threads/dim x 32 partials) ----
    {
        const int dim  = tid & 127;
        const int half = tid >> 7;
        const int k0   = half * 32;
        float dn = 0.f, num = 0.f;
        #pragma unroll 8
        for (int k = k0; k < k0 + 32; k++) {
            dn  += g_den0[b * GPB + k];
            num += g_part0[((size_t)b * GPB + k) * D_ + dim];
        }
        s_n[half][dim] = num;
        if (dim == 0) s_dn[half] = dn;
    }
    __syncthreads();
    if (tid < D_) {
        s_u[tid] = hidden[(size_t)b * D_ + tid]
                 + (s_n[0][tid] + s_n[1][tid]) / (s_dn[0] + s_dn[1]);
    }
    __syncthreads();

    // ---- hop-1 pass ----
    {
        const float4 u4 = reinterpret_cast<const float4*>(s_u)[lane];
        float4 acc = make_float4(0.f, 0.f, 0.f, 0.f);
        float den = 0.f;
        #pragma unroll
        for (int i = 0; i < 4; i++) {
            const float4 va = unpack4(ra[i]);
            const float4 vb = unpack4(rb[i]);
            float d = va.x * u4.x + va.y * u4.y + va.z * u4.z + va.w * u4.w;
            d = warpSum(d);
            const float e = __expf(d);
            acc.x += e * vb.x; acc.y += e * vb.y;
            acc.z += e * vb.z; acc.w += e * vb.w;
            den += e;
        }
        reinterpret_cast<float4*>(&s_pt[wid][0])[lane] = acc;
        if (lane == 0) s_den[wid] = den;
    }
    __syncthreads();
    if (tid < D_) {
        float v = 0.f;
        #pragma unroll
        for (int k = 0; k < 8; k++) v += s_pt[k][tid];
        g_part1[(size_t)blk * D_ + tid] = v;
    }
    if (tid == 0) {
        float dn = 0.f;
        #pragma unroll
        for (int k = 0; k < 8; k++) dn += s_den[k];
        g_den1[blk] = dn;
    }

    // ---- batch barrier A (monotonic ticket over 16 same-batch blocks) ----
    __threadfence();
    __syncthreads();
    if (tid == 0) {
        const unsigned arrive = atomicAdd(&g_cA[b], 1u) + 1u;
        const unsigned target = ((arrive + FSPL - 1u) / FSPL) * FSPL;
        while (*((volatile unsigned*)&g_cA[b]) < target) __nanosleep(32);
    }
    __syncthreads();
    __threadfence();

    // Prefetch hop-2 rows (C2, C3).
    #pragma unroll
    for (int i = 0; i < 4; i++) {
        const size_t r = rbase + (size_t)(wid * 4 + i) * (D_ / 4);
        ra[i] = g_bagh[bstr + r];        // C2
        rb[i] = g_bagh[2 * bstr + r];    // C3
    }

    // ---- Phase B: u2 reduce (2 threads/dim x 8 partials); u1 in s_u ----
    {
        const int dim  = tid & 127;
        const int half = tid >> 7;
        const int k0   = half * 8;
        float dn = 0.f, num = 0.f;
        #pragma unroll
        for (int k = k0; k < k0 + 8; k++) {
            dn  += g_den1[b * FSPL + k];
            num += g_part1[((size_t)b * FSPL + k) * D_ + dim];
        }
        s_n[half][dim] = num;
        if (dim == 0) s_dn[half] = dn;
    }
    __syncthreads();
    if (tid < D_) {
        s_u[tid] = s_u[tid]
                 + (s_n[0][tid] + s_n[1][tid]) / (s_dn[0] + s_dn[1]);
    }
    __syncthreads();

    // ---- hop-2 pass: logits -> OUT; partials for u3 ----
    {
        const float4 u4 = reinterpret_cast<const float4*>(s_u)[lane];
        float4 acc = make_float4(0.f, 0.f, 0.f, 0.f);
        float den = 0.f;
        #pragma unroll
        for (int i = 0; i < 4; i++) {
            const float4 va = unpack4(ra[i]);
            const float4 vb = unpack4(rb[i]);
            float d = va.x * u4.x + va.y * u4.y + va.z * u4.z + va.w * u4.w;
            d = warpSum(d);
            const float e = __expf(d);
            if (lane == 0) out[(size_t)b * M_ + sp * 32 + wid * 4 + i] = d;
            acc.x += e * vb.x; acc.y += e * vb.y;
            acc.z += e * vb.z; acc.w += e * vb.w;
            den += e;
        }
        reinterpret_cast<float4*>(&s_pt[wid][0])[lane] = acc;
        if (lane == 0) s_den[wid] = den;
    }
    __syncthreads();
    if (tid < D_) {
        float v = 0.f;
        #pragma unroll
        for (int k = 0; k < 8; k++) v += s_pt[k][tid];
        g_part2[(size_t)blk * D_ + tid] = v;
    }
    if (tid == 0) {
        float dn = 0.f;
        #pragma unroll
        for (int k = 0; k < 8; k++) dn += s_den[k];
        g_den2[blk] = dn;
    }
    __syncthreads();

    // ---- last-arriver (mod-16, monotonic) computes u3 -> OUT ----
    if (tid == 0) {
        __threadfence();
        const unsigned arrive = atomicAdd(&g_cB[b], 1u) + 1u;
        s_last = ((arrive % FSPL) == 0u);
    }
    __syncthreads();
    if (s_last) {
        __threadfence();   // acquire peers' partial writes
        if (tid < D_) {
            float dn = 0.f;
            #pragma unroll
            for (int k = 0; k < FSPL; k++) dn += g_den2[b * FSPL + k];
            float num = 0.f;
            #pragma unroll
            for (int k = 0; k < FSPL; k++) num += g_part2[((size_t)b * FSPL + k) * D_ + tid];
            out[(size_t)B_ * M_ + (size_t)b * D_ + tid] = s_u[tid] + num / dn;
        }
    }
}

extern "C" void kernel_launch(void* const* d_in, const int* in_sizes, int n_in,
                              void* d_out, int out_size)
{
    const int*   story  = (const int*)  d_in[0];   // [B, M, S] int32
    const float* hidden = (const float*)d_in[1];   // [B, 1, D] f32
    const float* C      = (const float*)d_in[2];   // [4, V, D] f32
    float* out = (float*)d_out;                    // [B*M] logits ++ [B*D] u

    k_gather<<<GBLK, 512>>>(story, hidden, C);     // hop-0 fused, 2 warps/(b,m)
    k_F     <<<FBLK, 256>>>(hidden, out);          // hops 1+2, per-batch barriers
}